// round 2
// baseline (speedup 1.0000x reference)
#include <cuda_runtime.h>
#include <math.h>

#define Bn 2
#define Cn 64
#define CQn 8
#define Hn 270
#define Wn 480
#define HWn (Hn*Wn)
#define NPIX (Bn*HWn)
#define Hp 272   // padded H stride for transposed layouts (16B-aligned rows)

// -------- scratch (device globals; allocation-free) --------
__device__ float g_q [Bn*CQn*HWn];        // [b][c8][h][w]
__device__ float g_k [Bn*CQn*HWn];
__device__ float g_v [Bn*Cn *HWn];        // [b][c][h][w]
__device__ float g_qT[Bn*Wn*CQn*Hp];      // [b][w][c8][h]
__device__ float g_kT[Bn*Wn*CQn*Hp];
__device__ float g_vT[Bn*Wn*Cn *Hp];      // [b][w][c][h]
__device__ float g_ow [Bn*Cn*HWn];        // unnorm out_w, [b][c][h][w]
__device__ float g_ohT[Bn*Wn*Cn*Hp];      // unnorm out_h, [b][w][c][h]
__device__ float g_sw [Bn*Hn*Wn];         // [b][h][w]
__device__ float g_sh [Bn*Wn*Hn];         // [b][w][h]
__device__ float g_inv[Bn*Hn*Wn];         // [b][h][w]

// ================= K1: fused q/k/v projection =================
// out tile: 80 output channels (q:0-7, k:8-15, v:16-79) x 64 pixels
__global__ __launch_bounds__(256) void proj_kernel(
    const float* __restrict__ x,
    const float* __restrict__ Wq, const float* __restrict__ bq,
    const float* __restrict__ Wk, const float* __restrict__ bk,
    const float* __restrict__ Wv, const float* __restrict__ bv)
{
    __shared__ float Ws[80][65];
    __shared__ float bs[80];
    __shared__ float xs[64][64];   // [c][px]
    int t = threadIdx.x;
    for (int i = t; i < 80*64; i += 256) {
        int o = i >> 6;
        float wv;
        if (o < 8)       wv = Wq[i];
        else if (o < 16) wv = Wk[i - 512];
        else             wv = Wv[i - 1024];
        Ws[o][i & 63] = wv;
    }
    if (t < 80) bs[t] = (t < 8) ? bq[t] : (t < 16 ? bk[t-8] : bv[t-16]);

    int p0 = blockIdx.x * 64;          // NPIX and HWn are multiples of 64
    int b  = p0 / HWn;
    int r0 = p0 - b*HWn;
    const float* xb = x + (size_t)b*Cn*HWn + r0;
    for (int i = t; i < 64*64; i += 256) {
        int c = i >> 6, j = i & 63;
        xs[c][j] = xb[(size_t)c*HWn + j];
    }
    __syncthreads();

    int to = t >> 4;   // 16 groups of 5 output channels
    int tp = t & 15;   // 4 pixels each (contiguous)
    float acc[5][4];
    #pragma unroll
    for (int i = 0; i < 5; i++) { acc[i][0]=acc[i][1]=acc[i][2]=acc[i][3]=0.f; }

    #pragma unroll 8
    for (int c = 0; c < 64; c++) {
        float4 xv = *(const float4*)&xs[c][tp*4];
        #pragma unroll
        for (int i = 0; i < 5; i++) {
            float wv = Ws[to*5+i][c];
            acc[i][0] += wv*xv.x; acc[i][1] += wv*xv.y;
            acc[i][2] += wv*xv.z; acc[i][3] += wv*xv.w;
        }
    }
    int rr = r0 + tp*4;
    #pragma unroll
    for (int i = 0; i < 5; i++) {
        int o = to*5 + i;
        float bb = bs[o];
        float4 res = make_float4(acc[i][0]+bb, acc[i][1]+bb, acc[i][2]+bb, acc[i][3]+bb);
        float* dst;
        if (o < 8)       dst = &g_q[(size_t)(b*CQn + o)*HWn + rr];
        else if (o < 16) dst = &g_k[(size_t)(b*CQn + o-8)*HWn + rr];
        else             dst = &g_v[(size_t)(b*Cn  + o-16)*HWn + rr];
        *(float4*)dst = res;
    }
}

// ================= K2: tiled transpose  [b][c][h][w] -> [b][w][c][h(pad Hp)] =================
__global__ __launch_bounds__(256) void transpose_kernel(int which, int nch)
{
    __shared__ float tile[32][33];
    const float* in; float* out;
    if (which == 0)      { in = g_q; out = g_qT; }
    else if (which == 1) { in = g_k; out = g_kT; }
    else                 { in = g_v; out = g_vT; }

    int bc = blockIdx.z;
    int b = bc / nch, ch = bc - b*nch;
    int w0 = blockIdx.x * 32, h0 = blockIdx.y * 32;
    int tx = threadIdx.x & 31, ty = threadIdx.x >> 5;   // ty: 0..7

    const float* plane = in + (size_t)(b*nch + ch)*HWn;
    #pragma unroll
    for (int k2 = 0; k2 < 4; k2++) {
        int h = h0 + ty + 8*k2, w = w0 + tx;
        tile[ty+8*k2][tx] = (h < Hn) ? plane[h*Wn + w] : 0.f;
    }
    __syncthreads();
    #pragma unroll
    for (int k2 = 0; k2 < 4; k2++) {
        int w = w0 + ty + 8*k2, h = h0 + tx;
        if (h < Hn)
            out[((size_t)(b*Wn + w)*nch + ch)*Hp + h] = tile[tx][ty+8*k2];
    }
}

// ================= K3: row attention (over width), unnormalized =================
// block = (wtile, h, b); 128 threads: g = t&3 (16 channels c=4*cc+g), wp = t>>2 (2 queries)
__global__ __launch_bounds__(128) void row_attn_kernel(const float* __restrict__ dww)
{
    const int b = blockIdx.z, h = blockIdx.y, wt = blockIdx.x;
    const int t = threadIdx.x;
    const int g = t & 3, wp = t >> 2;
    const int wl0 = wp*2, wl1 = wl0 + 1;
    const int wg0 = wt*64 + wl0, wg1 = wg0 + 1;

    __shared__ float q_s[CQn][64];
    __shared__ float k_s[CQn][64];
    __shared__ float v_s[64][68];   // [c][key] pitch 68 (16B-aligned, conflict-free)
    __shared__ float p_s[64][68];   // [query][key]
    __shared__ float dwt[Wn];

    for (int i = t; i < Wn; i += 128) dwt[i] = dww[i];   // row 0 = f(|d|)
    for (int i = t; i < CQn*64; i += 128) {
        int c8 = i >> 6, wl = i & 63;
        int wg = wt*64 + wl;
        q_s[c8][wl] = (wg < Wn) ? g_q[(size_t)(b*CQn+c8)*HWn + h*Wn + wg] : 0.f;
    }
    __syncthreads();

    float qr0[8], qr1[8];
    #pragma unroll
    for (int c8 = 0; c8 < 8; c8++) { qr0[c8] = q_s[c8][wl0]; qr1[c8] = q_s[c8][wl1]; }

    float acc0[16], acc1[16];
    #pragma unroll
    for (int i = 0; i < 16; i++) { acc0[i] = 0.f; acc1[i] = 0.f; }
    float s0 = 0.f, s1 = 0.f;

    for (int ch = 0; ch < 8; ch++) {
        const int v0 = ch*64;
        for (int i = t; i < CQn*64; i += 128) {
            int c8 = i >> 6, vl = i & 63;
            int vg = v0 + vl;
            k_s[c8][vl] = (vg < Wn) ? g_k[(size_t)(b*CQn+c8)*HWn + h*Wn + vg] : 0.f;
        }
        for (int i4 = t; i4 < 64*16; i4 += 128) {
            int c = i4 >> 4, vq = i4 & 15;
            int vg = v0 + vq*4;
            float4 val = make_float4(0.f,0.f,0.f,0.f);
            if (vg < Wn) val = *(const float4*)&g_v[(size_t)(b*Cn+c)*HWn + h*Wn + vg];
            *(float4*)&v_s[c][vq*4] = val;
        }
        __syncthreads();

        // logits + exp
        #pragma unroll
        for (int jj = 0; jj < 16; jj++) {
            int vl = g + jj*4;
            int vg = v0 + vl;
            float l0 = 0.f, l1 = 0.f;
            #pragma unroll
            for (int c8 = 0; c8 < 8; c8++) {
                float kv = k_s[c8][vl];
                l0 += qr0[c8]*kv; l1 += qr1[c8]*kv;
            }
            int d0 = abs(wg0 - vg); if (d0 > Wn-1) d0 = Wn-1;
            int d1 = abs(wg1 - vg); if (d1 > Wn-1) d1 = Wn-1;
            float p0 = (vg < Wn) ? __expf(l0*dwt[d0]) : 0.f;
            float p1 = (vg < Wn) ? __expf(l1*dwt[d1]) : 0.f;
            p_s[wl0][vl] = p0; p_s[wl1][vl] = p1;
            s0 += p0; s1 += p1;
        }
        __syncthreads();

        // accumulate out += P @ V
        #pragma unroll 4
        for (int vp4 = 0; vp4 < 16; vp4++) {
            float4 P0 = *(const float4*)&p_s[wl0][vp4*4];
            float4 P1 = *(const float4*)&p_s[wl1][vp4*4];
            #pragma unroll
            for (int cc = 0; cc < 16; cc++) {
                float4 V = *(const float4*)&v_s[cc*4+g][vp4*4];
                acc0[cc] += P0.x*V.x + P0.y*V.y + P0.z*V.z + P0.w*V.w;
                acc1[cc] += P1.x*V.x + P1.y*V.y + P1.z*V.z + P1.w*V.w;
            }
        }
        __syncthreads();
    }

    s0 += __shfl_xor_sync(0xffffffffu, s0, 1);
    s0 += __shfl_xor_sync(0xffffffffu, s0, 2);
    s1 += __shfl_xor_sync(0xffffffffu, s1, 1);
    s1 += __shfl_xor_sync(0xffffffffu, s1, 2);

    if (wg0 < Wn) {
        if (g == 0) g_sw[(b*Hn + h)*Wn + wg0] = s0;
        #pragma unroll
        for (int cc = 0; cc < 16; cc++)
            g_ow[(size_t)(b*Cn + cc*4+g)*HWn + h*Wn + wg0] = acc0[cc];
    }
    if (wg1 < Wn) {
        if (g == 0) g_sw[(b*Hn + h)*Wn + wg1] = s1;
        #pragma unroll
        for (int cc = 0; cc < 16; cc++)
            g_ow[(size_t)(b*Cn + cc*4+g)*HWn + h*Wn + wg1] = acc1[cc];
    }
}

// ================= K4: column attention (over height), diag masked, unnormalized =================
// block = (htile, w, b); uses transposed layouts
__global__ __launch_bounds__(128) void col_attn_kernel(const float* __restrict__ dwh)
{
    const int b = blockIdx.z, w = blockIdx.y, ht = blockIdx.x;
    const int t = threadIdx.x;
    const int g = t & 3, wp = t >> 2;
    const int hl0 = wp*2, hl1 = hl0 + 1;
    const int hg0 = ht*64 + hl0, hg1 = hg0 + 1;

    __shared__ float q_s[CQn][64];
    __shared__ float k_s[CQn][64];
    __shared__ float v_s[64][68];
    __shared__ float p_s[64][68];
    __shared__ float dwt[Hn];

    for (int i = t; i < Hn; i += 128) dwt[i] = dwh[i];
    for (int i = t; i < CQn*64; i += 128) {
        int c8 = i >> 6, hl = i & 63;
        int hg = ht*64 + hl;
        q_s[c8][hl] = (hg < Hn) ? g_qT[((size_t)(b*Wn+w)*CQn + c8)*Hp + hg] : 0.f;
    }
    __syncthreads();

    float qr0[8], qr1[8];
    #pragma unroll
    for (int c8 = 0; c8 < 8; c8++) { qr0[c8] = q_s[c8][hl0]; qr1[c8] = q_s[c8][hl1]; }

    float acc0[16], acc1[16];
    #pragma unroll
    for (int i = 0; i < 16; i++) { acc0[i] = 0.f; acc1[i] = 0.f; }
    float s0 = 0.f, s1 = 0.f;

    for (int ch = 0; ch < 5; ch++) {       // ceil(270/64)
        const int g0 = ch*64;
        for (int i = t; i < CQn*64; i += 128) {
            int c8 = i >> 6, gl = i & 63;
            int gg = g0 + gl;
            k_s[c8][gl] = (gg < Hn) ? g_kT[((size_t)(b*Wn+w)*CQn + c8)*Hp + gg] : 0.f;
        }
        for (int i4 = t; i4 < 64*16; i4 += 128) {
            int c = i4 >> 4, gq = i4 & 15;
            int gg4 = g0 + gq*4;
            float4 val = make_float4(0.f,0.f,0.f,0.f);
            if (gg4 < Hn)   // pad rows [270,272) are zero-initialized device globals
                val = *(const float4*)&g_vT[((size_t)(b*Wn+w)*Cn + c)*Hp + gg4];
            *(float4*)&v_s[c][gq*4] = val;
        }
        __syncthreads();

        #pragma unroll
        for (int jj = 0; jj < 16; jj++) {
            int gl = g + jj*4;
            int gg = g0 + gl;
            float l0 = 0.f, l1 = 0.f;
            #pragma unroll
            for (int c8 = 0; c8 < 8; c8++) {
                float kv = k_s[c8][gl];
                l0 += qr0[c8]*kv; l1 += qr1[c8]*kv;
            }
            int d0 = abs(hg0 - gg); if (d0 > Hn-1) d0 = Hn-1;
            int d1 = abs(hg1 - gg); if (d1 > Hn-1) d1 = Hn-1;
            float p0 = (gg < Hn && gg != hg0) ? __expf(l0*dwt[d0]) : 0.f;
            float p1 = (gg < Hn && gg != hg1) ? __expf(l1*dwt[d1]) : 0.f;
            p_s[hl0][gl] = p0; p_s[hl1][gl] = p1;
            s0 += p0; s1 += p1;
        }
        __syncthreads();

        #pragma unroll 4
        for (int gp4 = 0; gp4 < 16; gp4++) {
            float4 P0 = *(const float4*)&p_s[hl0][gp4*4];
            float4 P1 = *(const float4*)&p_s[hl1][gp4*4];
            #pragma unroll
            for (int cc = 0; cc < 16; cc++) {
                float4 V = *(const float4*)&v_s[cc*4+g][gp4*4];
                acc0[cc] += P0.x*V.x + P0.y*V.y + P0.z*V.z + P0.w*V.w;
                acc1[cc] += P1.x*V.x + P1.y*V.y + P1.z*V.z + P1.w*V.w;
            }
        }
        __syncthreads();
    }

    s0 += __shfl_xor_sync(0xffffffffu, s0, 1);
    s0 += __shfl_xor_sync(0xffffffffu, s0, 2);
    s1 += __shfl_xor_sync(0xffffffffu, s1, 1);
    s1 += __shfl_xor_sync(0xffffffffu, s1, 2);

    if (hg0 < Hn) {
        if (g == 0) g_sh[(b*Wn + w)*Hn + hg0] = s0;
        #pragma unroll
        for (int cc = 0; cc < 16; cc++)
            g_ohT[((size_t)(b*Wn+w)*Cn + cc*4+g)*Hp + hg0] = acc0[cc];
    }
    if (hg1 < Hn) {
        if (g == 0) g_sh[(b*Wn + w)*Hn + hg1] = s1;
        #pragma unroll
        for (int cc = 0; cc < 16; cc++)
            g_ohT[((size_t)(b*Wn+w)*Cn + cc*4+g)*Hp + hg1] = acc1[cc];
    }
}

// ================= K4.5: per-pixel 1/(s_h+s_w) =================
__global__ __launch_bounds__(256) void stats_kernel()
{
    int i = blockIdx.x*256 + threadIdx.x;
    if (i >= NPIX) return;
    int b = i / HWn, r = i - b*HWn;
    int h = r / Wn, w = r - h*Wn;
    float s = g_sw[i] + g_sh[(b*Wn + w)*Hn + h];
    g_inv[i] = 1.0f / s;
}

// ================= K5: combine (transpose-read out_h) + residual =================
__global__ __launch_bounds__(256) void combine_kernel(
    const float* __restrict__ x, const float* __restrict__ gamma_p,
    float* __restrict__ out)
{
    __shared__ float tile[32][33];
    int bc = blockIdx.z;
    int b = bc >> 6, c = bc & 63;
    int w0 = blockIdx.x * 32, h0 = blockIdx.y * 32;
    int tx = threadIdx.x & 31, ty = threadIdx.x >> 5;

    #pragma unroll
    for (int k2 = 0; k2 < 4; k2++) {
        int w = w0 + ty + 8*k2, h = h0 + tx;
        float v = 0.f;
        if (h < Hn) v = g_ohT[((size_t)(b*Wn+w)*Cn + c)*Hp + h];
        tile[ty+8*k2][tx] = v;
    }
    __syncthreads();
    float gamma = gamma_p[0];
    #pragma unroll
    for (int k2 = 0; k2 < 4; k2++) {
        int h = h0 + ty + 8*k2, w = w0 + tx;
        if (h >= Hn) continue;
        float oh = tile[tx][ty+8*k2];
        size_t idx = (size_t)(b*Cn + c)*HWn + h*Wn + w;
        float ow = g_ow[idx];
        float iv = g_inv[(b*Hn + h)*Wn + w];
        out[idx] = gamma * (oh + ow) * iv + x[idx];
    }
}

// ================= launch =================
extern "C" void kernel_launch(void* const* d_in, const int* in_sizes, int n_in,
                              void* d_out, int out_size)
{
    const float* x     = (const float*)d_in[0];
    const float* Wq    = (const float*)d_in[1];
    const float* bq    = (const float*)d_in[2];
    const float* Wk    = (const float*)d_in[3];
    const float* bk    = (const float*)d_in[4];
    const float* Wv    = (const float*)d_in[5];
    const float* bv    = (const float*)d_in[6];
    const float* gamma = (const float*)d_in[7];
    const float* dwh   = (const float*)d_in[8];
    const float* dww   = (const float*)d_in[9];
    float* out = (float*)d_out;

    proj_kernel<<<NPIX/64, 256>>>(x, Wq, bq, Wk, bk, Wv, bv);

    transpose_kernel<<<dim3(Wn/32, (Hn+31)/32, Bn*CQn), 256>>>(0, CQn);
    transpose_kernel<<<dim3(Wn/32, (Hn+31)/32, Bn*CQn), 256>>>(1, CQn);
    transpose_kernel<<<dim3(Wn/32, (Hn+31)/32, Bn*Cn ), 256>>>(2, Cn);

    row_attn_kernel<<<dim3(8, Hn, Bn), 128>>>(dww);
    col_attn_kernel<<<dim3(5, Wn, Bn), 128>>>(dwh);

    stats_kernel<<<(NPIX + 255)/256, 256>>>();

    combine_kernel<<<dim3(Wn/32, (Hn+31)/32, Bn*Cn), 256>>>(x, gamma, out);
}